// round 8
// baseline (speedup 1.0000x reference)
#include <cuda_runtime.h>

// left, right: [B, C, H, W] fp32 ; out: [B, C, D, H, W] fp32
#define BB 2
#define CC 32
#define HH 96
#define WW 320
#define DISP 48
#define W4 (WW / 4)              // 80 float4 per row
#define NTHREADS 512
#define PER_BLOCK (HH * W4)      // 7680 float4 outputs per (bc, d) block
#define ITERS (PER_BLOCK / NTHREADS)  // 15

__global__ __launch_bounds__(NTHREADS)
void diffvolume_kernel(const float* __restrict__ left,
                       const float* __restrict__ right,
                       float* __restrict__ out) {
    const int blk = blockIdx.x;          // bc*DISP + d
    const int bc  = blk / DISP;
    const int d   = blk - bc * DISP;

    const int r   = d & 3;               // block-constant misalignment
    const int qd  = d >> 2;
    const int off = (4 - r) & 3;         // element offset inside aligned float4

    const float* lpl = left  + (size_t)bc * HH * WW;
    const float* rpl = right + (size_t)bc * HH * WW;
    // Block writes the contiguous span out[bc, d, :, :] (122,880 bytes).
    float4* ob = (float4*)out + (size_t)blk * PER_BLOCK;

    const int t = threadIdx.x;

#pragma unroll
    for (int it = 0; it < ITERS; ++it) {
        const int i  = t + it * NTHREADS;    // 0 .. 7679, contiguous store idx
        const int h  = i / W4;
        const int w4 = i - h * W4;
        const int w0 = w4 * 4;

        const float4 lv = __ldg((const float4*)(lpl + h * WW) + w4);

        // Right window starts at element w0 - d. Aligned container float4:
        //   r==0: base4 = w4 - qd, off 0 ; r>0: base4 = w4 - qd - 1, off 4-r.
        // Negative bases clamp to 0; those values are masked by (w0+k >= d).
        int base4 = w4 - qd - (r != 0);
        const int b0 = base4 < 0 ? 0 : base4;
        const int b1 = base4 + 1 < 0 ? 0 : base4 + 1;
        const float4* rr4 = (const float4*)(rpl + h * WW);
        const float4 q0 = __ldg(rr4 + b0);
        const float4 q1 = __ldg(rr4 + b1);

        float v0, v1, v2, v3;
        switch (off) {                        // block-uniform branch
            case 0:  v0 = q0.x; v1 = q0.y; v2 = q0.z; v3 = q0.w; break;
            case 1:  v0 = q0.y; v1 = q0.z; v2 = q0.w; v3 = q1.x; break;
            case 2:  v0 = q0.z; v1 = q0.w; v2 = q1.x; v3 = q1.y; break;
            default: v0 = q0.w; v1 = q1.x; v2 = q1.y; v3 = q1.z; break;
        }

        float4 o;
        o.x = (w0 + 0 >= d) ? lv.x - v0 : 0.f;
        o.y = (w0 + 1 >= d) ? lv.y - v1 : 0.f;
        o.z = (w0 + 2 >= d) ? lv.z - v2 : 0.f;
        o.w = (w0 + 3 >= d) ? lv.w - v3 : 0.f;
        __stcs(ob + i, o);                    // .cs: proven load-bearing (R5/R7)
    }
}

extern "C" void kernel_launch(void* const* d_in, const int* in_sizes, int n_in,
                              void* d_out, int out_size) {
    const float* left  = (const float*)d_in[0];
    const float* right = (const float*)d_in[1];
    float* out = (float*)d_out;

    dim3 grid(BB * CC * DISP);   // 3072 blocks, one per (bc, d) output plane
    diffvolume_kernel<<<grid, NTHREADS>>>(left, right, out);
}

// round 9
// speedup vs baseline: 1.1043x; 1.1043x over previous
#include <cuda_runtime.h>

// left, right: [B, C, H, W] fp32 ; out: [B, C, D, H, W] fp32
#define BB 2
#define CC 32
#define HH 96
#define WW 320
#define DISP 48
#define W8 (WW / 8)            // 40 float8 slots per row
#define NTHREADS 160           // 40 w8-slots x 4 disparity groups
#define DG 12                  // disparities per group (48 / 4)

__global__ __launch_bounds__(NTHREADS)
void diffvolume_kernel(const float* __restrict__ left,
                       const float* __restrict__ right,
                       float* __restrict__ out) {
    const int row = blockIdx.x;              // bc*HH + h
    const int t = threadIdx.x;

    const int w8 = t % W8;                   // fixed output column (float8)
    const int dg = t / W8;                   // disparity group 0..3
    const int d0 = dg * DG;
    const int w0 = w8 * 8;

    const float* lrow = left  + (size_t)row * WW;
    const float* rrow = right + (size_t)row * WW;

    // Left operand: 8 floats, reused for all 12 disparities.
    const float4 la = __ldg((const float4*)(lrow + w0));
    const float4 lb = __ldg((const float4*)(lrow + w0 + 4));

    // Initial right window right[w0-d0 .. w0-d0+7]. w0 mult of 8, d0 mult of
    // 12 -> i0 mult of 4 (aligned float4 pair). Out-of-range values are
    // garbage but all consumers are masked by (w0+k >= d) == (src >= 0).
    int i0 = w0 - d0;
    int ia = i0 < 0 ? 0 : i0;
    int ib = i0 + 4 < 0 ? 0 : i0 + 4;
    const float4 qa = __ldg((const float4*)(rrow + ia));
    const float4 qb = __ldg((const float4*)(rrow + ib));
    float r0 = qa.x, r1 = qa.y, r2 = qa.z, r3 = qa.w;
    float r4 = qb.x, r5 = qb.y, r6 = qb.z, r7 = qb.w;

    // Prefetch all sliding right-operand scalars (front-batched MLP).
    float nr[DG - 1];
#pragma unroll
    for (int it = 0; it < DG - 1; ++it) {
        int si = w0 - (d0 + it) - 1;
        if (si < 0) si = 0;                  // clamped -> consumer is masked
        nr[it] = __ldg(rrow + si);
    }

    const int bc = row / HH;
    const int h  = row - bc * HH;

    // out[bc, d, h, w8] in float8 units: ((bc*DISP + d)*HH + h)*W8 + w8
    size_t obyte = ((size_t)((bc * DISP + d0) * HH + h) * W8 + w8) * 32u;
    float* obase = out;                      // 32B-aligned: offsets are mult 32

#pragma unroll
    for (int it = 0; it < DG; ++it) {
        const int d = d0 + it;
        const float o0 = (w0 + 0 >= d) ? la.x - r0 : 0.f;
        const float o1 = (w0 + 1 >= d) ? la.y - r1 : 0.f;
        const float o2 = (w0 + 2 >= d) ? la.z - r2 : 0.f;
        const float o3 = (w0 + 3 >= d) ? la.w - r3 : 0.f;
        const float o4 = (w0 + 4 >= d) ? lb.x - r4 : 0.f;
        const float o5 = (w0 + 5 >= d) ? lb.y - r5 : 0.f;
        const float o6 = (w0 + 6 >= d) ? lb.z - r6 : 0.f;
        const float o7 = (w0 + 7 >= d) ? lb.w - r7 : 0.f;

        // 256-bit streaming store (sm_100+): one STG.256 per 32B.
        asm volatile(
            "st.global.cs.v8.f32 [%0], {%1,%2,%3,%4,%5,%6,%7,%8};"
            :: "l"((char*)obase + obyte),
               "f"(o0), "f"(o1), "f"(o2), "f"(o3),
               "f"(o4), "f"(o5), "f"(o6), "f"(o7)
            : "memory");
        obyte += (size_t)HH * W8 * 32u;

        if (it < DG - 1) {
            // slide: window(d+1) = { right[w0-d-1], r0..r6 }
            r7 = r6; r6 = r5; r5 = r4; r4 = r3;
            r3 = r2; r2 = r1; r1 = r0; r0 = nr[it];
        }
    }
}

extern "C" void kernel_launch(void* const* d_in, const int* in_sizes, int n_in,
                              void* d_out, int out_size) {
    const float* left  = (const float*)d_in[0];
    const float* right = (const float*)d_in[1];
    float* out = (float*)d_out;

    dim3 grid(BB * CC * HH);   // 6144 blocks, one per (b, c, h) row pair
    diffvolume_kernel<<<grid, NTHREADS>>>(left, right, out);
}

// round 10
// speedup vs baseline: 1.2687x; 1.1488x over previous
#include <cuda_runtime.h>

// left, right: [B, C, H, W] fp32 ; out: [B, C, D, H, W] fp32
#define BB 2
#define CC 32
#define HH 96
#define WW 320
#define DISP 48
#define W4 (WW / 4)            // 80 float4 per row
#define NGROUPS 6              // disparity groups
#define DG (DISP / NGROUPS)    // 8 disparities per group
#define NTHREADS (W4 * NGROUPS)  // 480

__global__ __launch_bounds__(NTHREADS)
void diffvolume_kernel(const float* __restrict__ left,
                       const float* __restrict__ right,
                       float* __restrict__ out) {
    const int row = blockIdx.x;              // bc*HH + h
    const int t = threadIdx.x;

    const int w4 = t % W4;                   // fixed output column (float4)
    const int dg = t / W4;                   // disparity group 0..5
    const int d0 = dg * DG;                  // multiple of 8 -> 4-aligned
    const int w0 = w4 * 4;

    const float* lrow = left  + (size_t)row * WW;
    const float* rrow = right + (size_t)row * WW;

    // Left operand: one coalesced float4 load, reused for all 8 disparities.
    const float4 lv = __ldg((const float4*)(lrow + w0));

    // Initial right window for d = d0. Out-of-range values are garbage, but
    // every consumer is masked by (w0+k >= d) == (src >= 0). Clamp keeps
    // 16B alignment (w0, d0 are multiples of 4).
    int i0 = w0 - d0;
    if (i0 < 0) i0 = 0;
    const float4 q = __ldg((const float4*)(rrow + i0));
    float r0 = q.x, r1 = q.y, r2 = q.z, r3 = q.w;

    // Prefetch all sliding right-operand scalars up front (front-batched MLP).
    float nr[DG - 1];
#pragma unroll
    for (int it = 0; it < DG - 1; ++it) {
        int si = w0 - (d0 + it) - 1;
        if (si < 0) si = 0;                  // clamped -> consumer is masked
        nr[it] = __ldg(rrow + si);           // coalesced 128B per warp
    }

    const int bc = row / HH;
    const int h  = row - bc * HH;

    float4* out4 = (float4*)out;
    // out[bc, d, h, w4] = ((bc*DISP + d)*HH + h)*W4 + w4
    int oidx = ((bc * DISP + d0) * HH + h) * W4 + w4;

#pragma unroll
    for (int it = 0; it < DG; ++it) {
        const int d = d0 + it;
        float4 o;
        o.x = (w0 + 0 >= d) ? lv.x - r0 : 0.f;
        o.y = (w0 + 1 >= d) ? lv.y - r1 : 0.f;
        o.z = (w0 + 2 >= d) ? lv.z - r2 : 0.f;
        o.w = (w0 + 3 >= d) ? lv.w - r3 : 0.f;
        __stcs(&out4[oidx], o);              // evict-first streaming store:
        oidx += HH * W4;                     // proven load-bearing (R5/R7)

        if (it < DG - 1) {
            // slide: r(d+1) = { right[w0-d-1], r0, r1, r2 }
            r3 = r2; r2 = r1; r1 = r0; r0 = nr[it];
        }
    }
}

extern "C" void kernel_launch(void* const* d_in, const int* in_sizes, int n_in,
                              void* d_out, int out_size) {
    const float* left  = (const float*)d_in[0];
    const float* right = (const float*)d_in[1];
    float* out = (float*)d_out;

    dim3 grid(BB * CC * HH);   // 6144 blocks, one per (b, c, h) row pair
    diffvolume_kernel<<<grid, NTHREADS>>>(left, right, out);
}

// round 11
// speedup vs baseline: 1.2761x; 1.0058x over previous
#include <cuda_runtime.h>

// left, right: [B, C, H, W] fp32 ; out: [B, C, D, H, W] fp32
#define BB 2
#define CC 32
#define HH 96
#define WW 320
#define DISP 48
#define W4 (WW / 4)              // 80 float4 per row
#define NGROUPS 12               // disparity groups
#define DG (DISP / NGROUPS)      // 4 disparities per group
#define NTHREADS (W4 * NGROUPS)  // 960

__global__ __launch_bounds__(NTHREADS)
void diffvolume_kernel(const float* __restrict__ left,
                       const float* __restrict__ right,
                       float* __restrict__ out) {
    const int row = blockIdx.x;              // bc*HH + h
    const int t = threadIdx.x;

    const int w4 = t % W4;                   // fixed output column (float4)
    const int dg = t / W4;                   // disparity group 0..11
    const int d0 = dg * DG;                  // multiple of 4 -> aligned window
    const int w0 = w4 * 4;

    const float* lrow = left  + (size_t)row * WW;
    const float* rrow = right + (size_t)row * WW;

    // Left operand: one coalesced float4 load, reused for all 4 disparities.
    const float4 lv = __ldg((const float4*)(lrow + w0));

    // Initial right window for d = d0. Out-of-range values are garbage, but
    // every consumer is masked by (w0+k >= d) == (src >= 0). Clamp keeps
    // 16B alignment (w0, d0 are multiples of 4).
    int i0 = w0 - d0;
    if (i0 < 0) i0 = 0;
    const float4 q = __ldg((const float4*)(rrow + i0));
    float r0 = q.x, r1 = q.y, r2 = q.z, r3 = q.w;

    // Prefetch the 3 sliding right-operand scalars up front (front-batched).
    float nr[DG - 1];
#pragma unroll
    for (int it = 0; it < DG - 1; ++it) {
        int si = w0 - (d0 + it) - 1;
        if (si < 0) si = 0;                  // clamped -> consumer is masked
        nr[it] = __ldg(rrow + si);           // coalesced 128B per warp
    }

    const int bc = row / HH;
    const int h  = row - bc * HH;

    float4* out4 = (float4*)out;
    // out[bc, d, h, w4] = ((bc*DISP + d)*HH + h)*W4 + w4
    int oidx = ((bc * DISP + d0) * HH + h) * W4 + w4;

#pragma unroll
    for (int it = 0; it < DG; ++it) {
        const int d = d0 + it;
        float4 o;
        o.x = (w0 + 0 >= d) ? lv.x - r0 : 0.f;
        o.y = (w0 + 1 >= d) ? lv.y - r1 : 0.f;
        o.z = (w0 + 2 >= d) ? lv.z - r2 : 0.f;
        o.w = (w0 + 3 >= d) ? lv.w - r3 : 0.f;
        __stcs(&out4[oidx], o);              // evict-first streaming store:
        oidx += HH * W4;                     // proven load-bearing (R5/R7)

        if (it < DG - 1) {
            // slide: r(d+1) = { right[w0-d-1], r0, r1, r2 }
            r3 = r2; r2 = r1; r1 = r0; r0 = nr[it];
        }
    }
}

extern "C" void kernel_launch(void* const* d_in, const int* in_sizes, int n_in,
                              void* d_out, int out_size) {
    const float* left  = (const float*)d_in[0];
    const float* right = (const float*)d_in[1];
    float* out = (float*)d_out;

    dim3 grid(BB * CC * HH);   // 6144 blocks, one per (b, c, h) row pair
    diffvolume_kernel<<<grid, NTHREADS>>>(left, right, out);
}